// round 1
// baseline (speedup 1.0000x reference)
#include <cuda_runtime.h>
#include <math.h>

#define GAMMA 0.001f

// ---------------- scratch (static device allocations only) ----------------
__device__ __align__(256) float g_h1[4096 * 8 * 14 * 14];      // conv1 output (pooled)
__device__ __align__(256) float g_feats[4096 * 784];           // conv2 output (pooled, flattened)
__device__ __align__(256) float g_f2[4096];                    // row norms of feats
__device__ __align__(256) float g_s2[8192];                    // row norms of support
__device__ __align__(256) float g_partial[8 * 4096 * 4];       // per-M-chunk partial outputs

// ---------------- conv1: 1->8ch 3x3 SAME + bias + relu + 2x2 maxpool -------
__global__ __launch_bounds__(256) void conv1_kernel(
    const float* __restrict__ x, const float* __restrict__ w1, const float* __restrict__ b1)
{
    __shared__ float simg[784];   // 28x28
    __shared__ float sw[72];
    __shared__ float sb[8];
    const int n = blockIdx.x;
    const int tid = threadIdx.x;

    for (int i = tid; i < 784; i += 256) simg[i] = x[(size_t)n * 784 + i];
    if (tid < 72) sw[tid] = w1[tid];
    if (tid < 8)  sb[tid] = b1[tid];
    __syncthreads();

    if (tid < 196) {
        const int py = tid / 14, px = tid % 14;
        #pragma unroll
        for (int c = 0; c < 8; c++) {
            float best = 0.0f;  // relu outputs are >= 0
            #pragma unroll
            for (int sy = 0; sy < 2; sy++) {
                #pragma unroll
                for (int sx = 0; sx < 2; sx++) {
                    const int y = 2 * py + sy, xx = 2 * px + sx;
                    float acc = sb[c];
                    #pragma unroll
                    for (int dy = 0; dy < 3; dy++) {
                        const int iy = y + dy - 1;
                        if (iy < 0 || iy >= 28) continue;
                        #pragma unroll
                        for (int dx = 0; dx < 3; dx++) {
                            const int ix = xx + dx - 1;
                            if (ix < 0 || ix >= 28) continue;
                            acc += simg[iy * 28 + ix] * sw[c * 9 + dy * 3 + dx];
                        }
                    }
                    acc = fmaxf(acc, 0.0f);
                    best = fmaxf(best, acc);
                }
            }
            g_h1[(((size_t)n * 8 + c) * 14 + py) * 14 + px] = best;
        }
    }
}

// ---------------- conv2: 8->16ch 3x3 SAME + bias + relu + pool + f2 --------
__global__ __launch_bounds__(256) void conv2_kernel(
    const float* __restrict__ w2, const float* __restrict__ b2)
{
    __shared__ float sin_[1568];   // 8 x 14 x 14
    __shared__ float sw[1152];     // 16 x 8 x 3 x 3
    __shared__ float sb[16];
    __shared__ float red[256];
    const int n = blockIdx.x;
    const int tid = threadIdx.x;

    for (int i = tid; i < 1568; i += 256) sin_[i] = g_h1[(size_t)n * 1568 + i];
    for (int i = tid; i < 1152; i += 256) sw[i] = w2[i];
    if (tid < 16) sb[tid] = b2[tid];
    __syncthreads();

    float f2local = 0.0f;
    for (int idx = tid; idx < 784; idx += 256) {
        const int c = idx / 49;
        const int r = idx % 49;
        const int py = r / 7, px = r % 7;
        float best = 0.0f;
        #pragma unroll
        for (int sy = 0; sy < 2; sy++) {
            #pragma unroll
            for (int sx = 0; sx < 2; sx++) {
                const int y = 2 * py + sy, xx = 2 * px + sx;
                float acc = sb[c];
                #pragma unroll
                for (int dy = 0; dy < 3; dy++) {
                    const int iy = y + dy - 1;
                    if (iy < 0 || iy >= 14) continue;
                    #pragma unroll
                    for (int dx = 0; dx < 3; dx++) {
                        const int ix = xx + dx - 1;
                        if (ix < 0 || ix >= 14) continue;
                        const float iv0 = sin_[0 * 196 + iy * 14 + ix];
                        // inner loop over input channels
                        #pragma unroll
                        for (int ci = 0; ci < 8; ci++) {
                            acc += sin_[ci * 196 + iy * 14 + ix] *
                                   sw[((c * 8 + ci) * 3 + dy) * 3 + dx];
                        }
                        (void)iv0;
                    }
                }
                acc = fmaxf(acc, 0.0f);
                best = fmaxf(best, acc);
            }
        }
        g_feats[(size_t)n * 784 + idx] = best;
        f2local += best * best;
    }

    // block reduction for f2
    red[tid] = f2local;
    __syncthreads();
    for (int s = 128; s > 0; s >>= 1) {
        if (tid < s) red[tid] += red[tid + s];
        __syncthreads();
    }
    if (tid == 0) g_f2[n] = red[0];
}

// ---------------- s2: row norms of support (warp per row) ------------------
__global__ __launch_bounds__(256) void s2_kernel(const float* __restrict__ support)
{
    const int warp = (blockIdx.x * 256 + threadIdx.x) / 32;
    const int lane = threadIdx.x % 32;
    if (warp >= 8192) return;
    const float* row = support + (size_t)warp * 784;
    float s = 0.0f;
    for (int k = lane; k < 784; k += 32) {
        const float v = row[k];
        s += v * v;
    }
    #pragma unroll
    for (int off = 16; off > 0; off >>= 1)
        s += __shfl_down_sync(0xFFFFFFFFu, s, off);
    if (lane == 0) g_s2[warp] = s;
}

// ---------------- fused RBF GEMM + K@alpha ---------------------------------
// Grid: (4096/64, 8). Block 256 threads. Each block: 64-row feats tile x
// 1024-col support chunk. Accumulates K@alpha into registers (deterministic),
// writes per-chunk partials.
#define BN 64
#define BM 64
#define BK 16
#define MTILES 16   // 16 * 64 = 1024 support rows per chunk

__global__ __launch_bounds__(256) void rbf_gemm_kernel(
    const float* __restrict__ support, const float* __restrict__ alpha)
{
    __shared__ float As[BK][BN];
    __shared__ float Bs[BK][BM];
    __shared__ float Ks[BN][BM + 1];
    __shared__ float Al[BM][4];

    const int tid = threadIdx.x;
    const int tx = tid % 16;          // m direction
    const int ty = tid / 16;          // n direction
    const int n0 = blockIdx.x * BN;
    const int chunk = blockIdx.y;
    const int m_begin = chunk * (MTILES * BM);

    float f2r[4];
    #pragma unroll
    for (int i = 0; i < 4; i++) f2r[i] = g_f2[n0 + ty * 4 + i];

    float oacc0 = 0.f, oacc1 = 0.f, oacc2 = 0.f, oacc3 = 0.f;

    const int lr = tid >> 2;          // 0..63  (row within tile)
    const int lc = (tid & 3) << 2;    // 0,4,8,12 (k offset, float4)

    for (int mt = 0; mt < MTILES; mt++) {
        const int m0 = m_begin + mt * BM;

        float acc[4][4];
        #pragma unroll
        for (int i = 0; i < 4; i++)
            #pragma unroll
            for (int j = 0; j < 4; j++) acc[i][j] = 0.0f;

        for (int kt = 0; kt < 49; kt++) {
            const int k0 = kt * 16;
            // cooperative loads, transposed into [k][row] layout
            {
                const float4 va = *(const float4*)(g_feats + (size_t)(n0 + lr) * 784 + k0 + lc);
                As[lc + 0][lr] = va.x; As[lc + 1][lr] = va.y;
                As[lc + 2][lr] = va.z; As[lc + 3][lr] = va.w;
                const float4 vb = *(const float4*)(support + (size_t)(m0 + lr) * 784 + k0 + lc);
                Bs[lc + 0][lr] = vb.x; Bs[lc + 1][lr] = vb.y;
                Bs[lc + 2][lr] = vb.z; Bs[lc + 3][lr] = vb.w;
            }
            __syncthreads();
            #pragma unroll
            for (int kk = 0; kk < BK; kk++) {
                const float4 a = *(const float4*)&As[kk][ty * 4];
                const float4 b = *(const float4*)&Bs[kk][tx * 4];
                acc[0][0] += a.x * b.x; acc[0][1] += a.x * b.y;
                acc[0][2] += a.x * b.z; acc[0][3] += a.x * b.w;
                acc[1][0] += a.y * b.x; acc[1][1] += a.y * b.y;
                acc[1][2] += a.y * b.z; acc[1][3] += a.y * b.w;
                acc[2][0] += a.z * b.x; acc[2][1] += a.z * b.y;
                acc[2][2] += a.z * b.z; acc[2][3] += a.z * b.w;
                acc[3][0] += a.w * b.x; acc[3][1] += a.w * b.y;
                acc[3][2] += a.w * b.z; acc[3][3] += a.w * b.w;
            }
            __syncthreads();
        }

        // RBF kernel values -> smem
        #pragma unroll
        for (int j = 0; j < 4; j++) {
            const float s2v = g_s2[m0 + tx * 4 + j];
            #pragma unroll
            for (int i = 0; i < 4; i++) {
                const float d2 = f2r[i] + s2v - 2.0f * acc[i][j];
                Ks[ty * 4 + i][tx * 4 + j] = __expf(-GAMMA * d2);
            }
        }
        // alpha tile -> smem (64 rows x 4 classes)
        Al[tid >> 2][tid & 3] = alpha[(size_t)(m0 + (tid >> 2)) * 4 + (tid & 3)];
        __syncthreads();

        // deterministic K @ alpha: 64 threads, one per feats row
        if (tid < 64) {
            #pragma unroll 8
            for (int mm = 0; mm < BM; mm++) {
                const float kv = Ks[tid][mm];
                const float4 av = *(const float4*)&Al[mm][0];
                oacc0 += kv * av.x;
                oacc1 += kv * av.y;
                oacc2 += kv * av.z;
                oacc3 += kv * av.w;
            }
        }
        __syncthreads();
    }

    if (tid < 64) {
        const size_t o = ((size_t)chunk * 4096 + n0 + tid) * 4;
        g_partial[o + 0] = oacc0;
        g_partial[o + 1] = oacc1;
        g_partial[o + 2] = oacc2;
        g_partial[o + 3] = oacc3;
    }
}

// ---------------- final reduction over M-chunks ----------------------------
__global__ __launch_bounds__(256) void reduce_kernel(float* __restrict__ out)
{
    const int i = blockIdx.x * 256 + threadIdx.x;
    if (i >= 4096 * 4) return;
    float s = 0.0f;
    #pragma unroll
    for (int g = 0; g < 8; g++) s += g_partial[(size_t)g * 4096 * 4 + i];
    out[i] = s;
}

// ---------------- launcher -------------------------------------------------
extern "C" void kernel_launch(void* const* d_in, const int* in_sizes, int n_in,
                              void* d_out, int out_size)
{
    const float* x       = (const float*)d_in[0];  // [4096,1,28,28]
    const float* w1      = (const float*)d_in[1];  // [8,1,3,3]
    const float* b1      = (const float*)d_in[2];  // [8]
    const float* w2      = (const float*)d_in[3];  // [16,8,3,3]
    const float* b2      = (const float*)d_in[4];  // [16]
    const float* support = (const float*)d_in[5];  // [8192,784]
    const float* alpha   = (const float*)d_in[6];  // [8192,4]
    float* out = (float*)d_out;                    // [4096,4]

    conv1_kernel<<<4096, 256>>>(x, w1, b1);
    conv2_kernel<<<4096, 256>>>(w2, b2);
    s2_kernel<<<1024, 256>>>(support);
    rbf_gemm_kernel<<<dim3(64, 8), 256>>>(support, alpha);
    reduce_kernel<<<64, 256>>>(out);
}

// round 12
// speedup vs baseline: 4.2755x; 4.2755x over previous
#include <cuda_runtime.h>
#include <cuda_bf16.h>
#include <math.h>
#include <stdint.h>

#define GAMMA 0.001f

// ---------------- scratch (static device allocations only) ----------------
__device__ __align__(256) float g_f2[4096];                      // row norms of feats
__device__ __align__(256) float g_s2[8192];                      // row norms of support
__device__ __align__(256) __nv_bfloat16 g_featsbf[4096 * 832];   // feats bf16, K padded 784->832
__device__ __align__(256) __nv_bfloat16 g_supbf[8192 * 832];     // support bf16, padded
__device__ __align__(256) float g_partial[64 * 4096 * 4];        // per-support-chunk partials

// ======================= PTX helpers (baseline sm_80+ ISA only) ============
__device__ __forceinline__ uint32_t smem_u32(const void* p) {
    uint32_t a;
    asm("{ .reg .u64 t; cvta.to.shared.u64 t, %1; cvt.u32.u64 %0, t; }" : "=r"(a) : "l"(p));
    return a;
}
__device__ __forceinline__ void ldsm_x4(uint32_t& r0, uint32_t& r1, uint32_t& r2, uint32_t& r3,
                                        uint32_t addr) {
    asm volatile("ldmatrix.sync.aligned.m8n8.x4.shared.b16 {%0,%1,%2,%3}, [%4];"
                 : "=r"(r0), "=r"(r1), "=r"(r2), "=r"(r3) : "r"(addr));
}
__device__ __forceinline__ void mma_bf16(float* c, const uint32_t* a, uint32_t b0, uint32_t b1) {
    asm volatile("mma.sync.aligned.m16n8k16.row.col.f32.bf16.bf16.f32 "
                 "{%0,%1,%2,%3}, {%4,%5,%6,%7}, {%8,%9}, {%0,%1,%2,%3};"
                 : "+f"(c[0]), "+f"(c[1]), "+f"(c[2]), "+f"(c[3])
                 : "r"(a[0]), "r"(a[1]), "r"(a[2]), "r"(a[3]), "r"(b0), "r"(b1));
}

// -------- fused conv1+conv2 (+bias,relu,pool each) -> bf16 feats + f2 ------
__global__ __launch_bounds__(256) void fused_conv_kernel(
    const float* __restrict__ x,
    const float* __restrict__ w1, const float* __restrict__ b1,
    const float* __restrict__ w2, const float* __restrict__ b2)
{
    __shared__ float simg[784];    // 28x28 input
    __shared__ float sh1[1568];    // 8 x 14 x 14 stage-1 output
    __shared__ float sw1[72];
    __shared__ float sb1[8];
    __shared__ float sw2[1152];
    __shared__ float sb2[16];
    __shared__ float red[256];
    const int n = blockIdx.x;
    const int tid = threadIdx.x;

    for (int i = tid; i < 784; i += 256) simg[i] = x[(size_t)n * 784 + i];
    for (int i = tid; i < 1152; i += 256) sw2[i] = w2[i];
    if (tid < 72) sw1[tid] = w1[tid];
    if (tid < 8)  sb1[tid] = b1[tid];
    if (tid < 16) sb2[tid] = b2[tid];
    __syncthreads();

    // ---- stage 1 ----
    if (tid < 196) {
        const int py = tid / 14, px = tid % 14;
        #pragma unroll
        for (int c = 0; c < 8; c++) {
            float best = 0.0f;
            #pragma unroll
            for (int sy = 0; sy < 2; sy++) {
                #pragma unroll
                for (int sx = 0; sx < 2; sx++) {
                    const int y = 2 * py + sy, xx = 2 * px + sx;
                    float acc = sb1[c];
                    #pragma unroll
                    for (int dy = 0; dy < 3; dy++) {
                        const int iy = y + dy - 1;
                        if (iy < 0 || iy >= 28) continue;
                        #pragma unroll
                        for (int dx = 0; dx < 3; dx++) {
                            const int ix = xx + dx - 1;
                            if (ix < 0 || ix >= 28) continue;
                            acc += simg[iy * 28 + ix] * sw1[c * 9 + dy * 3 + dx];
                        }
                    }
                    best = fmaxf(best, fmaxf(acc, 0.0f));
                }
            }
            sh1[c * 196 + py * 14 + px] = best;
        }
    }
    __syncthreads();

    // ---- stage 2 ----
    float f2local = 0.0f;
    for (int idx = tid; idx < 784; idx += 256) {
        const int c = idx / 49;
        const int r = idx % 49;
        const int py = r / 7, px = r % 7;
        float best = 0.0f;
        #pragma unroll
        for (int sy = 0; sy < 2; sy++) {
            #pragma unroll
            for (int sx = 0; sx < 2; sx++) {
                const int y = 2 * py + sy, xx = 2 * px + sx;
                float acc = sb2[c];
                #pragma unroll
                for (int dy = 0; dy < 3; dy++) {
                    const int iy = y + dy - 1;
                    if (iy < 0 || iy >= 14) continue;
                    #pragma unroll
                    for (int dx = 0; dx < 3; dx++) {
                        const int ix = xx + dx - 1;
                        if (ix < 0 || ix >= 14) continue;
                        #pragma unroll
                        for (int ci = 0; ci < 8; ci++) {
                            acc += sh1[ci * 196 + iy * 14 + ix] *
                                   sw2[((c * 8 + ci) * 3 + dy) * 3 + dx];
                        }
                    }
                }
                best = fmaxf(best, fmaxf(acc, 0.0f));
            }
        }
        g_featsbf[(size_t)n * 832 + idx] = __float2bfloat16(best);
        f2local += best * best;
    }
    for (int i = 784 + tid; i < 832; i += 256)
        g_featsbf[(size_t)n * 832 + i] = __float2bfloat16(0.0f);

    red[tid] = f2local;
    __syncthreads();
    for (int s = 128; s > 0; s >>= 1) {
        if (tid < s) red[tid] += red[tid + s];
        __syncthreads();
    }
    if (tid == 0) g_f2[n] = red[0];
}

// ---------------- s2 + bf16 conversion of support -------------------------
__global__ __launch_bounds__(256) void s2_kernel(const float* __restrict__ support)
{
    const int warp = (blockIdx.x * 256 + threadIdx.x) / 32;
    const int lane = threadIdx.x % 32;
    if (warp >= 8192) return;
    const float* row = support + (size_t)warp * 784;
    __nv_bfloat16* brow = g_supbf + (size_t)warp * 832;
    float s = 0.0f;
    for (int k = lane; k < 784; k += 32) {
        const float v = row[k];
        s += v * v;
        brow[k] = __float2bfloat16(v);
    }
    for (int k = 784 + lane; k < 832; k += 32) brow[k] = __float2bfloat16(0.0f);
    #pragma unroll
    for (int off = 16; off > 0; off >>= 1)
        s += __shfl_down_sync(0xFFFFFFFFu, s, off);
    if (lane == 0) g_s2[warp] = s;
}

// ================= fused RBF GEMM via mma.sync (bf16 HMMA) =================
// Grid (32, 64), 256 threads (8 warps, 2x4). CTA tile: 128 feats rows x
// 128 support rows, K=832 in 26 chunks of 32, double-buffered smem.
// Warp tile 64x32 = 4x4 m16n8k16 fragments. Epilogue: kv=exp(-g*d2),
// K@alpha reduced in-register (fixed shfl sequence -> deterministic),
// cross-warp via smem overlapping the dead A/B buffers.
#define LDA 40                       // bf16 per smem row (32 + 8 pad = 80B)
#define TILE_E (128 * LDA)           // 5120 bf16 = 10240 B per buffer
#define KCHUNKS 26

__global__ __launch_bounds__(256) void rbf_mma_kernel(const float* __restrict__ alpha)
{
    __shared__ __align__(16) char smem[44032];
    // layout: [0, 20480) A double-buffer | [20480, 40960) B double-buffer
    //         [40960, 41472) f2 | [41472, 41984) s2 | [41984, 44032) alpha
    //         red[128][4][4] overlaps A after the K loop.
    __nv_bfloat16* As = (__nv_bfloat16*)(smem);
    __nv_bfloat16* Bs = (__nv_bfloat16*)(smem + 20480);
    float* f2s = (float*)(smem + 40960);
    float* s2s = (float*)(smem + 41472);
    float* als = (float*)(smem + 41984);
    float* redb = (float*)(smem);     // reuse after GEMM

    const int tid = threadIdx.x;
    const int lane = tid & 31;
    const int wid = tid >> 5;
    const int warp_m = wid >> 2;      // 0..1  (feats-row half)
    const int warp_n = wid & 3;       // 0..3  (support-col quarter)
    const int n0 = blockIdx.x * 128;  // feats rows
    const int m0 = blockIdx.y * 128;  // support rows
    const uint32_t sa = smem_u32(smem);

    if (tid < 128) { f2s[tid] = g_f2[n0 + tid]; s2s[tid] = g_s2[m0 + tid]; }
    *(float2*)(als + tid * 2) = *(const float2*)(alpha + (size_t)m0 * 4 + tid * 2);

    // ---- load chunk 0 into buffer 0 ----
    {
        int q = tid, row = q >> 2, seg = q & 3;
        *(uint4*)(As + row * LDA + seg * 8) =
            *(const uint4*)(g_featsbf + (size_t)(n0 + row) * 832 + seg * 8);
        *(uint4*)(Bs + row * LDA + seg * 8) =
            *(const uint4*)(g_supbf + (size_t)(m0 + row) * 832 + seg * 8);
        q = tid + 256; row = q >> 2; seg = q & 3;
        *(uint4*)(As + row * LDA + seg * 8) =
            *(const uint4*)(g_featsbf + (size_t)(n0 + row) * 832 + seg * 8);
        *(uint4*)(Bs + row * LDA + seg * 8) =
            *(const uint4*)(g_supbf + (size_t)(m0 + row) * 832 + seg * 8);
    }
    __syncthreads();

    float acc[4][4][4];
    #pragma unroll
    for (int mt = 0; mt < 4; mt++)
        #pragma unroll
        for (int nt = 0; nt < 4; nt++)
            #pragma unroll
            for (int r = 0; r < 4; r++) acc[mt][nt][r] = 0.0f;

    const int prow0 = tid >> 2, pseg0 = tid & 3;
    const int prow1 = (tid + 256) >> 2, pseg1 = (tid + 256) & 3;

    for (int c = 0; c < KCHUNKS; c++) {
        const int buf = c & 1;
        uint4 pa0, pa1, pb0, pb1;
        if (c < KCHUNKS - 1) {
            const int k0 = (c + 1) * 32;
            pa0 = *(const uint4*)(g_featsbf + (size_t)(n0 + prow0) * 832 + k0 + pseg0 * 8);
            pa1 = *(const uint4*)(g_featsbf + (size_t)(n0 + prow1) * 832 + k0 + pseg1 * 8);
            pb0 = *(const uint4*)(g_supbf + (size_t)(m0 + prow0) * 832 + k0 + pseg0 * 8);
            pb1 = *(const uint4*)(g_supbf + (size_t)(m0 + prow1) * 832 + k0 + pseg1 * 8);
        }

        const uint32_t abase = sa + buf * (TILE_E * 2);
        const uint32_t bbase = sa + 20480 + buf * (TILE_E * 2);
        #pragma unroll
        for (int ks = 0; ks < 2; ks++) {
            uint32_t af[4][4];
            #pragma unroll
            for (int mt = 0; mt < 4; mt++) {
                const uint32_t addr = abase +
                    (uint32_t)(warp_m * 64 + mt * 16 + (lane & 15)) * 80 +
                    ks * 32 + (lane >> 4) * 16;
                ldsm_x4(af[mt][0], af[mt][1], af[mt][2], af[mt][3], addr);
            }
            uint32_t bfm[2][4];
            #pragma unroll
            for (int p = 0; p < 2; p++) {
                const uint32_t addr = bbase +
                    (uint32_t)(warp_n * 32 + p * 16 + ((lane >> 4) << 3) + (lane & 7)) * 80 +
                    ks * 32 + ((lane >> 3) & 1) * 16;
                ldsm_x4(bfm[p][0], bfm[p][1], bfm[p][2], bfm[p][3], addr);
            }
            #pragma unroll
            for (int mt = 0; mt < 4; mt++)
                #pragma unroll
                for (int nt = 0; nt < 4; nt++)
                    mma_bf16(acc[mt][nt], af[mt],
                             bfm[nt >> 1][(nt & 1) * 2], bfm[nt >> 1][(nt & 1) * 2 + 1]);
        }

        if (c < KCHUNKS - 1) {
            const int nb = 1 - buf;
            *(uint4*)(As + nb * TILE_E + prow0 * LDA + pseg0 * 8) = pa0;
            *(uint4*)(As + nb * TILE_E + prow1 * LDA + pseg1 * 8) = pa1;
            *(uint4*)(Bs + nb * TILE_E + prow0 * LDA + pseg0 * 8) = pb0;
            *(uint4*)(Bs + nb * TILE_E + prow1 * LDA + pseg1 * 8) = pb1;
            __syncthreads();
        }
    }
    __syncthreads();   // A/B buffers dead; red buffer may be written

    // ---- epilogue: kv = exp(-g*(f2+s2-2D)); per-row K@alpha, fixed order ---
    #pragma unroll
    for (int mt = 0; mt < 4; mt++) {
        const int rA = warp_m * 64 + mt * 16 + (lane >> 2);
        const int rB = rA + 8;
        const float f2a = f2s[rA], f2b = f2s[rB];
        float oA0 = 0.f, oA1 = 0.f, oA2 = 0.f, oA3 = 0.f;
        float oB0 = 0.f, oB1 = 0.f, oB2 = 0.f, oB3 = 0.f;
        #pragma unroll
        for (int nt = 0; nt < 4; nt++) {
            const int c0 = warp_n * 32 + nt * 8 + (lane & 3) * 2;
            const float s20 = s2s[c0], s21 = s2s[c0 + 1];
            const float kA0 = __expf(-GAMMA * (f2a + s20 - 2.0f * acc[mt][nt][0]));
            const float kA1 = __expf(-GAMMA * (f2a + s21 - 2.0f * acc[mt][nt][1]));
            const float kB0 = __expf(-GAMMA * (f2b + s20 - 2.0f * acc[mt][nt][2]));
            const float kB1 = __expf(-GAMMA * (f2b + s21 - 2.0f * acc[mt][nt][3]));
            const float4 av0 = *(const float4*)(als + c0 * 4);
            const float4 av1 = *(const float4*)(als + (c0 + 1) * 4);
            oA0 += kA0 * av0.x + kA1 * av1.x;  oA1 += kA0 * av0.y + kA1 * av1.y;
            oA2 += kA0 * av0.z + kA1 * av1.z;  oA3 += kA0 * av0.w + kA1 * av1.w;
            oB0 += kB0 * av0.x + kB1 * av1.x;  oB1 += kB0 * av0.y + kB1 * av1.y;
            oB2 += kB0 * av0.z + kB1 * av1.z;  oB3 += kB0 * av0.w + kB1 * av1.w;
        }
        // reduce across the 4 lanes sharing a row (fixed shuffle sequence)
        #pragma unroll
        for (int d = 1; d < 4; d <<= 1) {
            oA0 += __shfl_xor_sync(0xFFFFFFFFu, oA0, d);
            oA1 += __shfl_xor_sync(0xFFFFFFFFu, oA1, d);
            oA2 += __shfl_xor_sync(0xFFFFFFFFu, oA2, d);
            oA3 += __shfl_xor_sync(0xFFFFFFFFu, oA3, d);
            oB0 += __shfl_xor_sync(0xFFFFFFFFu, oB0, d);
            oB1 += __shfl_xor_sync(0xFFFFFFFFu, oB1, d);
            oB2 += __shfl_xor_sync(0xFFFFFFFFu, oB2, d);
            oB3 += __shfl_xor_sync(0xFFFFFFFFu, oB3, d);
        }
        if ((lane & 3) == 0) {
            float* ra = redb + (rA * 4 + warp_n) * 4;
            ra[0] = oA0; ra[1] = oA1; ra[2] = oA2; ra[3] = oA3;
            float* rb = redb + (rB * 4 + warp_n) * 4;
            rb[0] = oB0; rb[1] = oB1; rb[2] = oB2; rb[3] = oB3;
        }
    }
    __syncthreads();

    if (tid < 128) {
        float o0 = 0.f, o1 = 0.f, o2 = 0.f, o3 = 0.f;
        #pragma unroll
        for (int w = 0; w < 4; w++) {
            const float4 v = *(const float4*)(redb + (tid * 4 + w) * 4);
            o0 += v.x; o1 += v.y; o2 += v.z; o3 += v.w;
        }
        const size_t o = ((size_t)blockIdx.y * 4096 + n0 + tid) * 4;
        g_partial[o + 0] = o0; g_partial[o + 1] = o1;
        g_partial[o + 2] = o2; g_partial[o + 3] = o3;
    }
}

// ---------------- final reduction over 64 support chunks -------------------
__global__ __launch_bounds__(256) void reduce_kernel(float* __restrict__ out)
{
    const int i = blockIdx.x * 256 + threadIdx.x;
    if (i >= 4096 * 4) return;
    float s = 0.0f;
    #pragma unroll
    for (int g = 0; g < 64; g++) s += g_partial[(size_t)g * 4096 * 4 + i];
    out[i] = s;
}

// ---------------- launcher -------------------------------------------------
extern "C" void kernel_launch(void* const* d_in, const int* in_sizes, int n_in,
                              void* d_out, int out_size)
{
    const float* x       = (const float*)d_in[0];  // [4096,1,28,28]
    const float* w1      = (const float*)d_in[1];  // [8,1,3,3]
    const float* b1      = (const float*)d_in[2];  // [8]
    const float* w2      = (const float*)d_in[3];  // [16,8,3,3]
    const float* b2      = (const float*)d_in[4];  // [16]
    const float* support = (const float*)d_in[5];  // [8192,784]
    const float* alpha   = (const float*)d_in[6];  // [8192,4]
    float* out = (float*)d_out;                    // [4096,4]

    fused_conv_kernel<<<4096, 256>>>(x, w1, b1, w2, b2);
    s2_kernel<<<1024, 256>>>(support);
    rbf_mma_kernel<<<dim3(32, 64), 256>>>(alpha);
    reduce_kernel<<<64, 256>>>(out);
}

// round 14
// speedup vs baseline: 4.4340x; 1.0371x over previous
#include <cuda_runtime.h>
#include <cuda_bf16.h>
#include <math.h>
#include <stdint.h>

#define GAMMA 0.001f

// ---------------- scratch (static device allocations only) ----------------
__device__ __align__(256) float g_f2[4096];                      // row norms of feats
__device__ __align__(256) float g_s2[8192];                      // row norms of support
__device__ __align__(256) __nv_bfloat16 g_featsbf[4096 * 832];   // feats bf16, K padded 784->832
__device__ __align__(256) __nv_bfloat16 g_supbf[8192 * 832];     // support bf16, padded
__device__ __align__(256) float g_partial[64 * 4096 * 4];        // per-support-chunk partials

// ======================= PTX helpers (baseline sm_80+ ISA only) ============
__device__ __forceinline__ uint32_t smem_u32(const void* p) {
    uint32_t a;
    asm("{ .reg .u64 t; cvta.to.shared.u64 t, %1; cvt.u32.u64 %0, t; }" : "=r"(a) : "l"(p));
    return a;
}
__device__ __forceinline__ void ldsm_x4(uint32_t& r0, uint32_t& r1, uint32_t& r2, uint32_t& r3,
                                        uint32_t addr) {
    asm volatile("ldmatrix.sync.aligned.m8n8.x4.shared.b16 {%0,%1,%2,%3}, [%4];"
                 : "=r"(r0), "=r"(r1), "=r"(r2), "=r"(r3) : "r"(addr));
}
__device__ __forceinline__ void mma_bf16(float* c, const uint32_t* a, uint32_t b0, uint32_t b1) {
    asm volatile("mma.sync.aligned.m16n8k16.row.col.f32.bf16.bf16.f32 "
                 "{%0,%1,%2,%3}, {%4,%5,%6,%7}, {%8,%9}, {%0,%1,%2,%3};"
                 : "+f"(c[0]), "+f"(c[1]), "+f"(c[2]), "+f"(c[3])
                 : "r"(a[0]), "r"(a[1]), "r"(a[2]), "r"(a[3]), "r"(b0), "r"(b1));
}
__device__ __forceinline__ void cp_async16(uint32_t smem_addr, const void* gptr) {
    asm volatile("cp.async.ca.shared.global [%0], [%1], 16;"
                 :: "r"(smem_addr), "l"(gptr) : "memory");
}
__device__ __forceinline__ void cp_commit() {
    asm volatile("cp.async.commit_group;" ::: "memory");
}
__device__ __forceinline__ void cp_wait0() {
    asm volatile("cp.async.wait_group 0;" ::: "memory");
}

// -------- fused conv1+conv2 (+bias,relu,pool each) -> bf16 feats + f2 ------
__global__ __launch_bounds__(256) void fused_conv_kernel(
    const float* __restrict__ x,
    const float* __restrict__ w1, const float* __restrict__ b1,
    const float* __restrict__ w2, const float* __restrict__ b2)
{
    __shared__ float simg[784];    // 28x28 input
    __shared__ float sh1[1568];    // 8 x 14 x 14 stage-1 output
    __shared__ float sw1[72];
    __shared__ float sb1[8];
    __shared__ float sw2[1152];
    __shared__ float sb2[16];
    __shared__ float red[256];
    const int n = blockIdx.x;
    const int tid = threadIdx.x;

    for (int i = tid; i < 784; i += 256) simg[i] = x[(size_t)n * 784 + i];
    for (int i = tid; i < 1152; i += 256) sw2[i] = w2[i];
    if (tid < 72) sw1[tid] = w1[tid];
    if (tid < 8)  sb1[tid] = b1[tid];
    if (tid < 16) sb2[tid] = b2[tid];
    __syncthreads();

    // ---- stage 1 ----
    if (tid < 196) {
        const int py = tid / 14, px = tid % 14;
        #pragma unroll
        for (int c = 0; c < 8; c++) {
            float best = 0.0f;
            #pragma unroll
            for (int sy = 0; sy < 2; sy++) {
                #pragma unroll
                for (int sx = 0; sx < 2; sx++) {
                    const int y = 2 * py + sy, xx = 2 * px + sx;
                    float acc = sb1[c];
                    #pragma unroll
                    for (int dy = 0; dy < 3; dy++) {
                        const int iy = y + dy - 1;
                        if (iy < 0 || iy >= 28) continue;
                        #pragma unroll
                        for (int dx = 0; dx < 3; dx++) {
                            const int ix = xx + dx - 1;
                            if (ix < 0 || ix >= 28) continue;
                            acc += simg[iy * 28 + ix] * sw1[c * 9 + dy * 3 + dx];
                        }
                    }
                    best = fmaxf(best, fmaxf(acc, 0.0f));
                }
            }
            sh1[c * 196 + py * 14 + px] = best;
        }
    }
    __syncthreads();

    // ---- stage 2 ----
    float f2local = 0.0f;
    for (int idx = tid; idx < 784; idx += 256) {
        const int c = idx / 49;
        const int r = idx % 49;
        const int py = r / 7, px = r % 7;
        float best = 0.0f;
        #pragma unroll
        for (int sy = 0; sy < 2; sy++) {
            #pragma unroll
            for (int sx = 0; sx < 2; sx++) {
                const int y = 2 * py + sy, xx = 2 * px + sx;
                float acc = sb2[c];
                #pragma unroll
                for (int dy = 0; dy < 3; dy++) {
                    const int iy = y + dy - 1;
                    if (iy < 0 || iy >= 14) continue;
                    #pragma unroll
                    for (int dx = 0; dx < 3; dx++) {
                        const int ix = xx + dx - 1;
                        if (ix < 0 || ix >= 14) continue;
                        #pragma unroll
                        for (int ci = 0; ci < 8; ci++) {
                            acc += sh1[ci * 196 + iy * 14 + ix] *
                                   sw2[((c * 8 + ci) * 3 + dy) * 3 + dx];
                        }
                    }
                }
                best = fmaxf(best, fmaxf(acc, 0.0f));
            }
        }
        g_featsbf[(size_t)n * 832 + idx] = __float2bfloat16(best);
        f2local += best * best;
    }
    for (int i = 784 + tid; i < 832; i += 256)
        g_featsbf[(size_t)n * 832 + i] = __float2bfloat16(0.0f);

    red[tid] = f2local;
    __syncthreads();
    for (int s = 128; s > 0; s >>= 1) {
        if (tid < s) red[tid] += red[tid + s];
        __syncthreads();
    }
    if (tid == 0) g_f2[n] = red[0];
}

// ---------------- s2 + bf16 conversion of support -------------------------
__global__ __launch_bounds__(256) void s2_kernel(const float* __restrict__ support)
{
    const int warp = (blockIdx.x * 256 + threadIdx.x) / 32;
    const int lane = threadIdx.x % 32;
    if (warp >= 8192) return;
    const float* row = support + (size_t)warp * 784;
    __nv_bfloat16* brow = g_supbf + (size_t)warp * 832;
    float s = 0.0f;
    for (int k = lane; k < 784; k += 32) {
        const float v = row[k];
        s += v * v;
        brow[k] = __float2bfloat16(v);
    }
    for (int k = 784 + lane; k < 832; k += 32) brow[k] = __float2bfloat16(0.0f);
    #pragma unroll
    for (int off = 16; off > 0; off >>= 1)
        s += __shfl_down_sync(0xFFFFFFFFu, s, off);
    if (lane == 0) g_s2[warp] = s;
}

// ================= fused RBF GEMM via mma.sync (bf16 HMMA) =================
// Grid (32, 64), 256 threads (8 warps, 2x4). CTA tile: 128 feats rows x
// 128 support rows, K=832 in 26 chunks of 32, cp.async double-buffered smem.
// Warp tile 64x32 = 4x4 m16n8k16 fragments. Epilogue: kv=exp(-g*d2),
// K@alpha reduced in-register (fixed shfl sequence -> deterministic),
// cross-warp via smem overlapping the dead A/B buffers.
// __launch_bounds__(256,2): cap regs at 128 so 2 CTAs/SM overlap barrier stalls.
#define LDA 40                       // bf16 per smem row (32 + 8 pad = 80B)
#define TILE_B 10240                 // bytes per single buffer (128 * 80)
#define KCHUNKS 26

__global__ __launch_bounds__(256, 2) void rbf_mma_kernel(const float* __restrict__ alpha)
{
    __shared__ __align__(16) char smem[44032];
    // layout: [0, 20480) A double-buffer | [20480, 40960) B double-buffer
    //         [40960, 41472) f2 | [41472, 41984) s2 | [41984, 44032) alpha
    //         red[128][4][4] overlaps A after the K loop.
    float* f2s = (float*)(smem + 40960);
    float* s2s = (float*)(smem + 41472);
    float* als = (float*)(smem + 41984);
    float* redb = (float*)(smem);     // reuse after GEMM

    const int tid = threadIdx.x;
    const int lane = tid & 31;
    const int wid = tid >> 5;
    const int wm = wid >> 2;          // 0..1  (feats-row half)
    const int wn = wid & 3;           // 0..3  (support-col quarter)
    const int n0 = blockIdx.x * 128;  // feats rows
    const int m0 = blockIdx.y * 128;  // support rows
    const uint32_t sa = smem_u32(smem);

    if (tid < 128) { f2s[tid] = g_f2[n0 + tid]; s2s[tid] = g_s2[m0 + tid]; }
    *(float2*)(als + tid * 2) = *(const float2*)(alpha + (size_t)m0 * 4 + tid * 2);

    const int prow0 = tid >> 2, pseg0 = tid & 3;
    const int prow1 = (tid + 256) >> 2, pseg1 = (tid + 256) & 3;

    // ---- prologue: chunk 0 -> buffer 0 via cp.async ----
    cp_async16(sa + (uint32_t)(prow0 * 80 + pseg0 * 16),
               g_featsbf + (size_t)(n0 + prow0) * 832 + pseg0 * 8);
    cp_async16(sa + (uint32_t)(prow1 * 80 + pseg1 * 16),
               g_featsbf + (size_t)(n0 + prow1) * 832 + pseg1 * 8);
    cp_async16(sa + 20480u + (uint32_t)(prow0 * 80 + pseg0 * 16),
               g_supbf + (size_t)(m0 + prow0) * 832 + pseg0 * 8);
    cp_async16(sa + 20480u + (uint32_t)(prow1 * 80 + pseg1 * 16),
               g_supbf + (size_t)(m0 + prow1) * 832 + pseg1 * 8);
    cp_commit();
    cp_wait0();
    __syncthreads();

    float acc[4][4][4];
    #pragma unroll
    for (int mt = 0; mt < 4; mt++)
        #pragma unroll
        for (int nt = 0; nt < 4; nt++)
            #pragma unroll
            for (int r = 0; r < 4; r++) acc[mt][nt][r] = 0.0f;

    for (int c = 0; c < KCHUNKS; c++) {
        // issue prefetch of chunk c+1 into the other buffer (async)
        if (c < KCHUNKS - 1) {
            const int k0 = (c + 1) * 32;
            const uint32_t nb = (uint32_t)((c + 1) & 1) * TILE_B;
            cp_async16(sa + nb + (uint32_t)(prow0 * 80 + pseg0 * 16),
                       g_featsbf + (size_t)(n0 + prow0) * 832 + k0 + pseg0 * 8);
            cp_async16(sa + nb + (uint32_t)(prow1 * 80 + pseg1 * 16),
                       g_featsbf + (size_t)(n0 + prow1) * 832 + k0 + pseg1 * 8);
            cp_async16(sa + 20480u + nb + (uint32_t)(prow0 * 80 + pseg0 * 16),
                       g_supbf + (size_t)(m0 + prow0) * 832 + k0 + pseg0 * 8);
            cp_async16(sa + 20480u + nb + (uint32_t)(prow1 * 80 + pseg1 * 16),
                       g_supbf + (size_t)(m0 + prow1) * 832 + k0 + pseg1 * 8);
            cp_commit();
        }

        const uint32_t abase = sa + (uint32_t)(c & 1) * TILE_B;
        const uint32_t bbase = sa + 20480u + (uint32_t)(c & 1) * TILE_B;
        #pragma unroll
        for (int ks = 0; ks < 2; ks++) {
            uint32_t af[4][4];
            #pragma unroll
            for (int mt = 0; mt < 4; mt++) {
                const uint32_t addr = abase +
                    (uint32_t)(wm * 64 + mt * 16 + (lane & 15)) * 80 +
                    ks * 32 + (lane >> 4) * 16;
                ldsm_x4(af[mt][0], af[mt][1], af[mt][2], af[mt][3], addr);
            }
            uint32_t bfm[2][4];
            #pragma unroll
            for (int p = 0; p < 2; p++) {
                const uint32_t addr = bbase +
                    (uint32_t)(wn * 32 + p * 16 + ((lane >> 4) << 3) + (lane & 7)) * 80 +
                    ks * 32 + ((lane >> 3) & 1) * 16;
                ldsm_x4(bfm[p][0], bfm[p][1], bfm[p][2], bfm[p][3], addr);
            }
            #pragma unroll
            for (int mt = 0; mt < 4; mt++)
                #pragma unroll
                for (int nt = 0; nt < 4; nt++)
                    mma_bf16(acc[mt][nt], af[mt],
                             bfm[nt >> 1][(nt & 1) * 2], bfm[nt >> 1][(nt & 1) * 2 + 1]);
        }

        if (c < KCHUNKS - 1) {
            cp_wait0();
            __syncthreads();
        }
    }
    __syncthreads();   // A/B buffers dead; red buffer may be written

    // ---- epilogue: kv = exp(-g*(f2+s2-2D)); per-row K@alpha, fixed order ---
    #pragma unroll
    for (int mt = 0; mt < 4; mt++) {
        const int rA = wm * 64 + mt * 16 + (lane >> 2);
        const int rB = rA + 8;
        const float f2a = f2s[rA], f2b = f2s[rB];
        float oA0 = 0.f, oA1 = 0.f, oA2 = 0.f, oA3 = 0.f;
        float oB0 = 0.f, oB1 = 0.f, oB2 = 0.f, oB3 = 0.f;
        #pragma unroll
        for (int nt = 0; nt < 4; nt++) {
            const int c0 = wn * 32 + nt * 8 + (lane & 3) * 2;
            const float s20 = s2s[c0], s21 = s2s[c0 + 1];
            const float kA0 = __expf(-GAMMA * (f2a + s20 - 2.0f * acc[mt][nt][0]));
            const float kA1 = __expf(-GAMMA * (f2a + s21 - 2.0f * acc[mt][nt][1]));
            const float kB0 = __expf(-GAMMA * (f2b + s20 - 2.0f * acc[mt][nt][2]));
            const float kB1 = __expf(-GAMMA * (f2b + s21 - 2.0f * acc[mt][nt][3]));
            const float4 av0 = *(const float4*)(als + c0 * 4);
            const float4 av1 = *(const float4*)(als + (c0 + 1) * 4);
            oA0 += kA0 * av0.x + kA1 * av1.x;  oA1 += kA0 * av0.y + kA1 * av1.y;
            oA2 += kA0 * av0.z + kA1 * av1.z;  oA3 += kA0 * av0.w + kA1 * av1.w;
            oB0 += kB0 * av0.x + kB1 * av1.x;  oB1 += kB0 * av0.y + kB1 * av1.y;
            oB2 += kB0 * av0.z + kB1 * av1.z;  oB3 += kB0 * av0.w + kB1 * av1.w;
        }
        // reduce across the 4 lanes sharing a row (fixed shuffle sequence)
        #pragma unroll
        for (int d = 1; d < 4; d <<= 1) {
            oA0 += __shfl_xor_sync(0xFFFFFFFFu, oA0, d);
            oA1 += __shfl_xor_sync(0xFFFFFFFFu, oA1, d);
            oA2 += __shfl_xor_sync(0xFFFFFFFFu, oA2, d);
            oA3 += __shfl_xor_sync(0xFFFFFFFFu, oA3, d);
            oB0 += __shfl_xor_sync(0xFFFFFFFFu, oB0, d);
            oB1 += __shfl_xor_sync(0xFFFFFFFFu, oB1, d);
            oB2 += __shfl_xor_sync(0xFFFFFFFFu, oB2, d);
            oB3 += __shfl_xor_sync(0xFFFFFFFFu, oB3, d);
        }
        if ((lane & 3) == 0) {
            float* ra = redb + (rA * 4 + wn) * 4;
            ra[0] = oA0; ra[1] = oA1; ra[2] = oA2; ra[3] = oA3;
            float* rb = redb + (rB * 4 + wn) * 4;
            rb[0] = oB0; rb[1] = oB1; rb[2] = oB2; rb[3] = oB3;
        }
    }
    __syncthreads();

    if (tid < 128) {
        float o0 = 0.f, o1 = 0.f, o2 = 0.f, o3 = 0.f;
        #pragma unroll
        for (int w = 0; w < 4; w++) {
            const float4 v = *(const float4*)(redb + (tid * 4 + w) * 4);
            o0 += v.x; o1 += v.y; o2 += v.z; o3 += v.w;
        }
        const size_t o = ((size_t)blockIdx.y * 4096 + n0 + tid) * 4;
        g_partial[o + 0] = o0; g_partial[o + 1] = o1;
        g_partial[o + 2] = o2; g_partial[o + 3] = o3;
    }
}

// ---------------- final reduction over 64 support chunks -------------------
__global__ __launch_bounds__(256) void reduce_kernel(float* __restrict__ out)
{
    const int i = blockIdx.x * 256 + threadIdx.x;
    if (i >= 4096 * 4) return;
    float s = 0.0f;
    #pragma unroll
    for (int g = 0; g < 64; g++) s += g_partial[(size_t)g * 4096 * 4 + i];
    out[i] = s;
}

// ---------------- launcher -------------------------------------------------
extern "C" void kernel_launch(void* const* d_in, const int* in_sizes, int n_in,
                              void* d_out, int out_size)
{
    const float* x       = (const float*)d_in[0];  // [4096,1,28,28]
    const float* w1      = (const float*)d_in[1];  // [8,1,3,3]
    const float* b1      = (const float*)d_in[2];  // [8]
    const float* w2      = (const float*)d_in[3];  // [16,8,3,3]
    const float* b2      = (const float*)d_in[4];  // [16]
    const float* support = (const float*)d_in[5];  // [8192,784]
    const float* alpha   = (const float*)d_in[6];  // [8192,4]
    float* out = (float*)d_out;                    // [4096,4]

    fused_conv_kernel<<<4096, 256>>>(x, w1, b1, w2, b2);
    s2_kernel<<<1024, 256>>>(support);
    rbf_mma_kernel<<<dim3(32, 64), 256>>>(alpha);
    reduce_kernel<<<64, 256>>>(out);
}

// round 17
// speedup vs baseline: 6.1619x; 1.3897x over previous
#include <cuda_runtime.h>
#include <cuda_bf16.h>
#include <math.h>
#include <stdint.h>

#define GAMMA 0.001f

// ---------------- scratch (static device allocations only) ----------------
__device__ __align__(256) float g_f2[4096];                      // row norms of feats
__device__ __align__(256) float g_s2[8192];                      // row norms of support
__device__ __align__(256) __nv_bfloat16 g_featsbf[4096 * 832];   // feats bf16, K padded 784->832
__device__ __align__(256) __nv_bfloat16 g_supbf[8192 * 832];     // support bf16, padded
__device__ __align__(256) float g_partial[64 * 4096 * 4];        // per-support-chunk partials

// ======================= PTX helpers (baseline sm_80+ ISA only) ============
__device__ __forceinline__ uint32_t smem_u32(const void* p) {
    uint32_t a;
    asm("{ .reg .u64 t; cvta.to.shared.u64 t, %1; cvt.u32.u64 %0, t; }" : "=r"(a) : "l"(p));
    return a;
}
__device__ __forceinline__ void ldsm_x4(uint32_t& r0, uint32_t& r1, uint32_t& r2, uint32_t& r3,
                                        uint32_t addr) {
    asm volatile("ldmatrix.sync.aligned.m8n8.x4.shared.b16 {%0,%1,%2,%3}, [%4];"
                 : "=r"(r0), "=r"(r1), "=r"(r2), "=r"(r3) : "r"(addr));
}
__device__ __forceinline__ void mma_bf16(float* c, const uint32_t* a, uint32_t b0, uint32_t b1) {
    asm volatile("mma.sync.aligned.m16n8k16.row.col.f32.bf16.bf16.f32 "
                 "{%0,%1,%2,%3}, {%4,%5,%6,%7}, {%8,%9}, {%0,%1,%2,%3};"
                 : "+f"(c[0]), "+f"(c[1]), "+f"(c[2]), "+f"(c[3])
                 : "r"(a[0]), "r"(a[1]), "r"(a[2]), "r"(a[3]), "r"(b0), "r"(b1));
}
__device__ __forceinline__ void cp_async16(uint32_t smem_addr, const void* gptr) {
    asm volatile("cp.async.ca.shared.global [%0], [%1], 16;"
                 :: "r"(smem_addr), "l"(gptr) : "memory");
}
__device__ __forceinline__ void cp_commit() {
    asm volatile("cp.async.commit_group;" ::: "memory");
}
__device__ __forceinline__ void cp_wait0() {
    asm volatile("cp.async.wait_group 0;" ::: "memory");
}

// -------- fused conv1+conv2 -> bf16 feats + f2 (zero-padded smem) ----------
// SAME conv == zero padding, so padded tiles are bit-exact and the inner
// loops carry no boundary predicates at all.
__global__ __launch_bounds__(256) void fused_conv_kernel(
    const float* __restrict__ x,
    const float* __restrict__ w1, const float* __restrict__ b1,
    const float* __restrict__ w2, const float* __restrict__ b2)
{
    __shared__ float simg[900];          // 30x30, image at [1..28][1..28]
    __shared__ float sh1[8][16][16];     // stage-1 out, data at [1..14][1..14]
    __shared__ float sw1[72];
    __shared__ float sb1[8];
    __shared__ float sw2[1152];
    __shared__ float sb2[16];
    __shared__ float red[256];
    const int n = blockIdx.x;
    const int tid = threadIdx.x;

    // zero-init padded buffers (borders must be 0)
    for (int i = tid; i < 900; i += 256) simg[i] = 0.0f;
    for (int i = tid; i < 2048; i += 256) ((float*)sh1)[i] = 0.0f;
    for (int i = tid; i < 1152; i += 256) sw2[i] = w2[i];
    if (tid < 72) sw1[tid] = w1[tid];
    if (tid < 8)  sb1[tid] = b1[tid];
    if (tid < 16) sb2[tid] = b2[tid];
    __syncthreads();

    // load image into padded interior
    for (int i = tid; i < 784; i += 256) {
        const int r = i / 28, cc = i % 28;
        simg[(r + 1) * 30 + cc + 1] = x[(size_t)n * 784 + i];
    }
    __syncthreads();

    // ---- stage 1: all 256 threads over 1568 (c,py,px) items ----
    for (int idx = tid; idx < 1568; idx += 256) {
        const int c = idx / 196;
        const int r = idx % 196;
        const int py = r / 14, px = r % 14;
        const float* wc = sw1 + c * 9;
        float best = 0.0f;
        #pragma unroll
        for (int sy = 0; sy < 2; sy++) {
            #pragma unroll
            for (int sx = 0; sx < 2; sx++) {
                const int y = 2 * py + sy, xx = 2 * px + sx;
                // padded: input pixel (y+dy-1, xx+dx-1) lives at [(y+dy)*30 + xx+dx]
                float acc = sb1[c];
                #pragma unroll
                for (int dy = 0; dy < 3; dy++)
                    #pragma unroll
                    for (int dx = 0; dx < 3; dx++)
                        acc += simg[(y + dy) * 30 + xx + dx] * wc[dy * 3 + dx];
                best = fmaxf(best, fmaxf(acc, 0.0f));
            }
        }
        sh1[c][py + 1][px + 1] = best;
    }
    __syncthreads();

    // ---- stage 2: 784 (c,py,px) items, no predicates ----
    float f2local = 0.0f;
    for (int idx = tid; idx < 784; idx += 256) {
        const int c = idx / 49;
        const int r = idx % 49;
        const int py = r / 7, px = r % 7;
        float best = 0.0f;
        #pragma unroll
        for (int sy = 0; sy < 2; sy++) {
            #pragma unroll
            for (int sx = 0; sx < 2; sx++) {
                const int y = 2 * py + sy, xx = 2 * px + sx;
                float acc = sb2[c];
                #pragma unroll
                for (int ci = 0; ci < 8; ci++) {
                    const float* wcc = sw2 + (c * 8 + ci) * 9;
                    #pragma unroll
                    for (int dy = 0; dy < 3; dy++)
                        #pragma unroll
                        for (int dx = 0; dx < 3; dx++)
                            acc += sh1[ci][y + dy][xx + dx] * wcc[dy * 3 + dx];
                }
                best = fmaxf(best, fmaxf(acc, 0.0f));
            }
        }
        g_featsbf[(size_t)n * 832 + idx] = __float2bfloat16(best);
        f2local += best * best;
    }
    for (int i = 784 + tid; i < 832; i += 256)
        g_featsbf[(size_t)n * 832 + i] = __float2bfloat16(0.0f);

    red[tid] = f2local;
    __syncthreads();
    for (int s = 128; s > 0; s >>= 1) {
        if (tid < s) red[tid] += red[tid + s];
        __syncthreads();
    }
    if (tid == 0) g_f2[n] = red[0];
}

// ---------------- s2 + bf16 conversion of support -------------------------
__global__ __launch_bounds__(256) void s2_kernel(const float* __restrict__ support)
{
    const int warp = (blockIdx.x * 256 + threadIdx.x) / 32;
    const int lane = threadIdx.x % 32;
    if (warp >= 8192) return;
    const float* row = support + (size_t)warp * 784;
    __nv_bfloat16* brow = g_supbf + (size_t)warp * 832;
    float s = 0.0f;
    for (int k = lane; k < 784; k += 32) {
        const float v = row[k];
        s += v * v;
        brow[k] = __float2bfloat16(v);
    }
    for (int k = 784 + lane; k < 832; k += 32) brow[k] = __float2bfloat16(0.0f);
    #pragma unroll
    for (int off = 16; off > 0; off >>= 1)
        s += __shfl_down_sync(0xFFFFFFFFu, s, off);
    if (lane == 0) g_s2[warp] = s;
}

// ================= fused RBF GEMM via mma.sync (bf16 HMMA) =================
// Grid (32, 64), 256 threads (8 warps, 2x4). CTA tile: 128 feats rows x
// 128 support rows, K=832 in 26 chunks of 32, cp.async double-buffered smem.
// Warp tile 64x32 = 4x4 m16n8k16 fragments. Epilogue: kv=exp(-g*d2),
// K@alpha reduced in-register (fixed shfl sequence -> deterministic),
// cross-warp via smem overlapping the dead A/B buffers.
#define LDA 40                       // bf16 per smem row (32 + 8 pad = 80B)
#define TILE_B 10240                 // bytes per single buffer (128 * 80)
#define KCHUNKS 26

__global__ __launch_bounds__(256, 2) void rbf_mma_kernel(const float* __restrict__ alpha)
{
    __shared__ __align__(16) char smem[44032];
    // layout: [0, 20480) A double-buffer | [20480, 40960) B double-buffer
    //         [40960, 41472) f2 | [41472, 41984) s2 | [41984, 44032) alpha
    //         red[128][4][4] overlaps A after the K loop.
    float* f2s = (float*)(smem + 40960);
    float* s2s = (float*)(smem + 41472);
    float* als = (float*)(smem + 41984);
    float* redb = (float*)(smem);     // reuse after GEMM

    const int tid = threadIdx.x;
    const int lane = tid & 31;
    const int wid = tid >> 5;
    const int wm = wid >> 2;          // 0..1  (feats-row half)
    const int wn = wid & 3;           // 0..3  (support-col quarter)
    const int n0 = blockIdx.x * 128;  // feats rows
    const int m0 = blockIdx.y * 128;  // support rows
    const uint32_t sa = smem_u32(smem);

    if (tid < 128) { f2s[tid] = g_f2[n0 + tid]; s2s[tid] = g_s2[m0 + tid]; }
    *(float2*)(als + tid * 2) = *(const float2*)(alpha + (size_t)m0 * 4 + tid * 2);

    const int prow0 = tid >> 2, pseg0 = tid & 3;
    const int prow1 = (tid + 256) >> 2, pseg1 = (tid + 256) & 3;

    // ---- prologue: chunk 0 -> buffer 0 via cp.async ----
    cp_async16(sa + (uint32_t)(prow0 * 80 + pseg0 * 16),
               g_featsbf + (size_t)(n0 + prow0) * 832 + pseg0 * 8);
    cp_async16(sa + (uint32_t)(prow1 * 80 + pseg1 * 16),
               g_featsbf + (size_t)(n0 + prow1) * 832 + pseg1 * 8);
    cp_async16(sa + 20480u + (uint32_t)(prow0 * 80 + pseg0 * 16),
               g_supbf + (size_t)(m0 + prow0) * 832 + pseg0 * 8);
    cp_async16(sa + 20480u + (uint32_t)(prow1 * 80 + pseg1 * 16),
               g_supbf + (size_t)(m0 + prow1) * 832 + pseg1 * 8);
    cp_commit();
    cp_wait0();
    __syncthreads();

    float acc[4][4][4];
    #pragma unroll
    for (int mt = 0; mt < 4; mt++)
        #pragma unroll
        for (int nt = 0; nt < 4; nt++)
            #pragma unroll
            for (int r = 0; r < 4; r++) acc[mt][nt][r] = 0.0f;

    for (int c = 0; c < KCHUNKS; c++) {
        // issue prefetch of chunk c+1 into the other buffer (async)
        if (c < KCHUNKS - 1) {
            const int k0 = (c + 1) * 32;
            const uint32_t nb = (uint32_t)((c + 1) & 1) * TILE_B;
            cp_async16(sa + nb + (uint32_t)(prow0 * 80 + pseg0 * 16),
                       g_featsbf + (size_t)(n0 + prow0) * 832 + k0 + pseg0 * 8);
            cp_async16(sa + nb + (uint32_t)(prow1 * 80 + pseg1 * 16),
                       g_featsbf + (size_t)(n0 + prow1) * 832 + k0 + pseg1 * 8);
            cp_async16(sa + 20480u + nb + (uint32_t)(prow0 * 80 + pseg0 * 16),
                       g_supbf + (size_t)(m0 + prow0) * 832 + k0 + pseg0 * 8);
            cp_async16(sa + 20480u + nb + (uint32_t)(prow1 * 80 + pseg1 * 16),
                       g_supbf + (size_t)(m0 + prow1) * 832 + k0 + pseg1 * 8);
            cp_commit();
        }

        const uint32_t abase = sa + (uint32_t)(c & 1) * TILE_B;
        const uint32_t bbase = sa + 20480u + (uint32_t)(c & 1) * TILE_B;
        #pragma unroll
        for (int ks = 0; ks < 2; ks++) {
            uint32_t af[4][4];
            #pragma unroll
            for (int mt = 0; mt < 4; mt++) {
                const uint32_t addr = abase +
                    (uint32_t)(wm * 64 + mt * 16 + (lane & 15)) * 80 +
                    ks * 32 + (lane >> 4) * 16;
                ldsm_x4(af[mt][0], af[mt][1], af[mt][2], af[mt][3], addr);
            }
            uint32_t bfm[2][4];
            #pragma unroll
            for (int p = 0; p < 2; p++) {
                const uint32_t addr = bbase +
                    (uint32_t)(wn * 32 + p * 16 + ((lane >> 4) << 3) + (lane & 7)) * 80 +
                    ks * 32 + ((lane >> 3) & 1) * 16;
                ldsm_x4(bfm[p][0], bfm[p][1], bfm[p][2], bfm[p][3], addr);
            }
            #pragma unroll
            for (int mt = 0; mt < 4; mt++)
                #pragma unroll
                for (int nt = 0; nt < 4; nt++)
                    mma_bf16(acc[mt][nt], af[mt],
                             bfm[nt >> 1][(nt & 1) * 2], bfm[nt >> 1][(nt & 1) * 2 + 1]);
        }

        if (c < KCHUNKS - 1) {
            cp_wait0();
            __syncthreads();
        }
    }
    __syncthreads();   // A/B buffers dead; red buffer may be written

    // ---- epilogue: kv = exp(-g*(f2+s2-2D)); per-row K@alpha, fixed order ---
    #pragma unroll
    for (int mt = 0; mt < 4; mt++) {
        const int rA = wm * 64 + mt * 16 + (lane >> 2);
        const int rB = rA + 8;
        const float f2a = f2s[rA], f2b = f2s[rB];
        float oA0 = 0.f, oA1 = 0.f, oA2 = 0.f, oA3 = 0.f;
        float oB0 = 0.f, oB1 = 0.f, oB2 = 0.f, oB3 = 0.f;
        #pragma unroll
        for (int nt = 0; nt < 4; nt++) {
            const int c0 = wn * 32 + nt * 8 + (lane & 3) * 2;
            const float s20 = s2s[c0], s21 = s2s[c0 + 1];
            const float kA0 = __expf(-GAMMA * (f2a + s20 - 2.0f * acc[mt][nt][0]));
            const float kA1 = __expf(-GAMMA * (f2a + s21 - 2.0f * acc[mt][nt][1]));
            const float kB0 = __expf(-GAMMA * (f2b + s20 - 2.0f * acc[mt][nt][2]));
            const float kB1 = __expf(-GAMMA * (f2b + s21 - 2.0f * acc[mt][nt][3]));
            const float4 av0 = *(const float4*)(als + c0 * 4);
            const float4 av1 = *(const float4*)(als + (c0 + 1) * 4);
            oA0 += kA0 * av0.x + kA1 * av1.x;  oA1 += kA0 * av0.y + kA1 * av1.y;
            oA2 += kA0 * av0.z + kA1 * av1.z;  oA3 += kA0 * av0.w + kA1 * av1.w;
            oB0 += kB0 * av0.x + kB1 * av1.x;  oB1 += kB0 * av0.y + kB1 * av1.y;
            oB2 += kB0 * av0.z + kB1 * av1.z;  oB3 += kB0 * av0.w + kB1 * av1.w;
        }
        // reduce across the 4 lanes sharing a row (fixed shuffle sequence)
        #pragma unroll
        for (int d = 1; d < 4; d <<= 1) {
            oA0 += __shfl_xor_sync(0xFFFFFFFFu, oA0, d);
            oA1 += __shfl_xor_sync(0xFFFFFFFFu, oA1, d);
            oA2 += __shfl_xor_sync(0xFFFFFFFFu, oA2, d);
            oA3 += __shfl_xor_sync(0xFFFFFFFFu, oA3, d);
            oB0 += __shfl_xor_sync(0xFFFFFFFFu, oB0, d);
            oB1 += __shfl_xor_sync(0xFFFFFFFFu, oB1, d);
            oB2 += __shfl_xor_sync(0xFFFFFFFFu, oB2, d);
            oB3 += __shfl_xor_sync(0xFFFFFFFFu, oB3, d);
        }
        if ((lane & 3) == 0) {
            float* ra = redb + (rA * 4 + wn) * 4;
            ra[0] = oA0; ra[1] = oA1; ra[2] = oA2; ra[3] = oA3;
            float* rb = redb + (rB * 4 + wn) * 4;
            rb[0] = oB0; rb[1] = oB1; rb[2] = oB2; rb[3] = oB3;
        }
    }
    __syncthreads();

    if (tid < 128) {
        float o0 = 0.f, o1 = 0.f, o2 = 0.f, o3 = 0.f;
        #pragma unroll
        for (int w = 0; w < 4; w++) {
            const float4 v = *(const float4*)(redb + (tid * 4 + w) * 4);
            o0 += v.x; o1 += v.y; o2 += v.z; o3 += v.w;
        }
        const size_t o = ((size_t)blockIdx.y * 4096 + n0 + tid) * 4;
        g_partial[o + 0] = o0; g_partial[o + 1] = o1;
        g_partial[o + 2] = o2; g_partial[o + 3] = o3;
    }
}

// ---------------- final reduction over 64 support chunks -------------------
__global__ __launch_bounds__(256) void reduce_kernel(float* __restrict__ out)
{
    const int i = blockIdx.x * 256 + threadIdx.x;
    if (i >= 4096 * 4) return;
    float s = 0.0f;
    #pragma unroll
    for (int g = 0; g < 64; g++) s += g_partial[(size_t)g * 4096 * 4 + i];
    out[i] = s;
}

// ---------------- launcher -------------------------------------------------
extern "C" void kernel_launch(void* const* d_in, const int* in_sizes, int n_in,
                              void* d_out, int out_size)
{
    const float* x       = (const float*)d_in[0];  // [4096,1,28,28]
    const float* w1      = (const float*)d_in[1];  // [8,1,3,3]
    const float* b1      = (const float*)d_in[2];  // [8]
    const float* w2      = (const float*)d_in[3];  // [16,8,3,3]
    const float* b2      = (const float*)d_in[4];  // [16]
    const float* support = (const float*)d_in[5];  // [8192,784]
    const float* alpha   = (const float*)d_in[6];  // [8192,4]
    float* out = (float*)d_out;                    // [4096,4]

    fused_conv_kernel<<<4096, 256>>>(x, w1, b1, w2, b2);
    s2_kernel<<<1024, 256>>>(support);
    rbf_mma_kernel<<<dim3(32, 64), 256>>>(alpha);
    reduce_kernel<<<64, 256>>>(out);
}